// round 12
// baseline (speedup 1.0000x reference)
#include <cuda_runtime.h>
#include <math.h>

#define NUM_BINS    128
#define NUM_NETS    100000
#define NUM_NODES   200000
#define NUM_MOVABLE 180000
#define NUM_PINS    400000
#define NREP        8               // replicas of each diff array

#define SB       7.8125f            // bin size (1000/128), exact in fp32
#define INV_SB   0.128f             // approx 1/SB; corrected in bin_of
#define BIN_AREA 61.03515625f       // SB*SB, exact
#define CXU (1.0f / (BIN_AREA * 1.5f))
#define CYU (1.0f / (BIN_AREA * 1.4f))

// Scratch. All zero at load; scan kernel re-zeroes each invocation.
__device__ __align__(16) float2 g_de[NREP][NUM_BINS * NUM_BINS];  // even-y pairs
__device__ __align__(16) float2 g_do[NREP][NUM_BINS * NUM_BINS];  // odd-y pairs, slot k = bin k+1
__device__ float2 g_pp[NUM_PINS];                            // interleaved pin coords
__device__ float2 g_pref[NUM_BINS * NUM_BINS];               // after y-prefix
__device__ float  g_util[NUM_BINS * NUM_BINS];               // final util [x*128+y]
__device__ int    g_ctr;                                     // scan grid barrier (reset by node_kernel)

__device__ __forceinline__ int bin_of(float v) {
    int b = (int)(v * INV_SB);
    b = max(0, min(NUM_BINS - 1, b));
    if (v < (float)b * SB) b--;
    else if (v >= (float)(b + 1) * SB) b++;
    return max(0, min(NUM_BINS - 1, b));
}

__device__ __forceinline__ void red_add4(float2* addr, float a0, float b0,
                                         float a1, float b1) {
    asm volatile("red.global.add.v4.f32 [%0], {%1, %2, %3, %4};"
                 :: "l"(addr), "f"(a0), "f"(b0), "f"(a1), "f"(b1) : "memory");
}

// Interleave pin coords: g_pp[p] = (x_p, y_p). Fully coalesced.
__global__ void prep_kernel(const float* __restrict__ pin_pos) {
    int i = blockIdx.x * blockDim.x + threadIdx.x;
    if (i < NUM_PINS)
        g_pp[i] = make_float2(__ldg(pin_pos + i), __ldg(pin_pos + i + NUM_PINS));
}

// One v4 RED covering logical bins (y, y+1) of x-row `row`, replica `rep`.
__device__ __forceinline__ void emit_pair(int rep, int row, int y,
                                          float a0, float b0, float a1, float b1) {
    if ((y & 1) == 0) {
        red_add4(&g_de[rep][row * NUM_BINS + y], a0, b0, a1, b1);
    } else {
        red_add4(&g_do[rep][row * NUM_BINS + (y - 1)], a0, b0, a1, b1);
    }
}

// Quad-reduced bbox -> 4 v4 updates (this lane's 2); lane q owns x-row q.
__device__ __forceinline__ void process_net(int n, int q, float w,
                                            float xmn, float xmx,
                                            float ymn, float ymx) {
    float dx = xmx - xmn, dy = ymx - ymn;
    float cx = (dy > 0.f) ? (w / dy) : 0.f;   // scales map_x
    float cy = (dx > 0.f) ? (w / dx) : 0.f;   // scales map_y
    if (cx == 0.f && cy == 0.f) return;       // also catches empty nets (inf bbox)

    int x0 = bin_of(xmn), x1 = bin_of(xmx);
    int y0 = bin_of(ymn), y1 = bin_of(ymx);

    float v0x = (float)(x0 + 1) * SB - xmn;
    float v1x = xmx - (float)x1 * SB;
    float v0y = (float)(y0 + 1) * SB - ymn;
    float v1y = ymx - (float)y1 * SB;

    float yv0 = v0y, yv1 = SB - v0y, yv2 = v1y - SB, yv3 = -v1y;

    int   xp   = ((q & 2) ? x1 : x0) + (q & 1);
    float base = (q & 2) ? (v1x - SB) : v0x;
    float alt  = (q & 2) ? (-v1x)     : (SB - v0x);
    float xv   = (q & 1) ? alt : base;

    if (xp < NUM_BINS) {
        int rep = n & (NREP - 1);
        float a = xv * cx, b = xv * cy;
        emit_pair(rep, xp, y0, a * yv0, b * yv0, a * yv1, b * yv1);
        emit_pair(rep, xp, y1, a * yv2, b * yv2, a * yv3, b * yv3);
    }
}

// One quad of lanes handles TWO nets (2k, 2k+1): each lane gathers ONE
// interleaved float2 per net (half the scattered wavefronts of 2x4B),
// then two quad shuffle-reductions and emissions.
__global__ void net_kernel(const float* __restrict__ net_weights,
                           const int*   __restrict__ netpin_start,
                           const int*   __restrict__ flat_netpin) {
    int gid  = blockIdx.x * blockDim.x + threadIdx.x;
    int pair = gid >> 2;           // net pair id
    int q    = gid & 3;            // lane-in-quad
    int n0   = pair * 2;
    if (n0 >= NUM_NETS) return;
    int n1 = n0 + 1;               // NUM_NETS is even

    int s0 = __ldg(netpin_start + n0);
    int e0 = __ldg(netpin_start + n0 + 1);
    int s1 = __ldg(netpin_start + n1);
    int e1 = __ldg(netpin_start + n1 + 1);

    float xmn0 = 3.4e38f, xmx0 = -3.4e38f, ymn0 = 3.4e38f, ymx0 = -3.4e38f;
    float xmn1 = 3.4e38f, xmx1 = -3.4e38f, ymn1 = 3.4e38f, ymx1 = -3.4e38f;

    if ((e0 - s0 == 4) && (e1 - s1 == 4)) {   // hot path for this dataset
        int p0 = __ldg(flat_netpin + s0 + q);
        int p1 = __ldg(flat_netpin + s1 + q);
        float2 c0 = g_pp[p0];
        float2 c1 = g_pp[p1];
        xmn0 = c0.x; xmx0 = c0.x; ymn0 = c0.y; ymx0 = c0.y;
        xmn1 = c1.x; xmx1 = c1.x; ymn1 = c1.y; ymx1 = c1.y;
    } else {                                   // general fallback
        for (int i = s0 + q; i < e0; i += 4) {
            float2 c = g_pp[__ldg(flat_netpin + i)];
            xmn0 = fminf(xmn0, c.x); xmx0 = fmaxf(xmx0, c.x);
            ymn0 = fminf(ymn0, c.y); ymx0 = fmaxf(ymx0, c.y);
        }
        for (int i = s1 + q; i < e1; i += 4) {
            float2 c = g_pp[__ldg(flat_netpin + i)];
            xmn1 = fminf(xmn1, c.x); xmx1 = fmaxf(xmx1, c.x);
            ymn1 = fminf(ymn1, c.y); ymx1 = fmaxf(ymx1, c.y);
        }
    }

    #pragma unroll
    for (int o = 1; o <= 2; o <<= 1) {
        xmn0 = fminf(xmn0, __shfl_xor_sync(0xffffffffu, xmn0, o));
        xmx0 = fmaxf(xmx0, __shfl_xor_sync(0xffffffffu, xmx0, o));
        ymn0 = fminf(ymn0, __shfl_xor_sync(0xffffffffu, ymn0, o));
        ymx0 = fmaxf(ymx0, __shfl_xor_sync(0xffffffffu, ymx0, o));
        xmn1 = fminf(xmn1, __shfl_xor_sync(0xffffffffu, xmn1, o));
        xmx1 = fmaxf(xmx1, __shfl_xor_sync(0xffffffffu, xmx1, o));
        ymn1 = fminf(ymn1, __shfl_xor_sync(0xffffffffu, ymn1, o));
        ymx1 = fmaxf(ymx1, __shfl_xor_sync(0xffffffffu, ymx1, o));
    }

    float w0 = __ldg(net_weights + n0);
    float w1 = __ldg(net_weights + n1);

    process_net(n0, q, w0, xmn0, xmx0, ymn0, ymx0);
    process_net(n1, q, w1, xmn1, xmx1, ymn1, ymx1);
}

__device__ __forceinline__ float2 block_scan_128(float2 v, float2* wsum) {
    int t = threadIdx.x, lane = t & 31, w = t >> 5;
    #pragma unroll
    for (int o = 1; o < 32; o <<= 1) {
        float ax = __shfl_up_sync(0xffffffffu, v.x, o);
        float ay = __shfl_up_sync(0xffffffffu, v.y, o);
        if (lane >= o) { v.x += ax; v.y += ay; }
    }
    if (lane == 31) wsum[w] = v;
    __syncthreads();
    float ox = 0.f, oy = 0.f;
    #pragma unroll
    for (int k = 0; k < 3; k++)
        if (w > k) { ox += wsum[k].x; oy += wsum[k].y; }
    v.x += ox; v.y += oy;
    return v;
}

// 128 blocks (all wave-1 resident). Phase 1: front-batch ALL 32 replica loads
// for slot t (MLP 32 vs pending-RMW latency), sum, zero exactly what was read,
// shift odd-phase sums by one thread (shfl + smem at warp seams) to realign
// logical bins, y-prefix scan. Grid barrier. Phase 2: x-prefix + util.
__global__ void scan_fused_kernel() {
    __shared__ float2 wsum[4];
    __shared__ float2 wdo[4];
    int b = blockIdx.x, t = threadIdx.x;
    int lane = t & 31, w = t >> 5;
    int idx = b * NUM_BINS + t;

    float2 de[NREP], dd[NREP];
    #pragma unroll
    for (int r = 0; r < NREP; r++) de[r] = g_de[r][idx];
    #pragma unroll
    for (int r = 0; r < NREP; r++) dd[r] = g_do[r][idx];

    float2 v  = make_float2(0.f, 0.f);
    float2 vo = make_float2(0.f, 0.f);
    #pragma unroll
    for (int r = 0; r < NREP; r++) {
        v.x  += de[r].x;  v.y  += de[r].y;
        vo.x += dd[r].x;  vo.y += dd[r].y;
    }
    #pragma unroll
    for (int r = 0; r < NREP; r++) {
        g_de[r][idx] = make_float2(0.f, 0.f);
        g_do[r][idx] = make_float2(0.f, 0.f);
    }

    // logical bin t = de_sum(t) + do_sum(t-1)
    float sx = __shfl_up_sync(0xffffffffu, vo.x, 1);
    float sy = __shfl_up_sync(0xffffffffu, vo.y, 1);
    if (lane == 31) wdo[w] = vo;
    __syncthreads();
    if (lane == 0) {
        if (w > 0) { sx = wdo[w - 1].x; sy = wdo[w - 1].y; }
        else       { sx = 0.f;          sy = 0.f; }
    }
    v.x += sx; v.y += sy;

    v = block_scan_128(v, wsum);
    g_pref[idx] = v;

    __threadfence();
    __syncthreads();
    if (t == 0) {
        atomicAdd(&g_ctr, 1);
        while (atomicAdd(&g_ctr, 0) < NUM_BINS) __nanosleep(40);
    }
    __syncthreads();
    __threadfence();

    float2 c;
    {
        const float2* p = g_pref + t * NUM_BINS + b;
        asm volatile("ld.global.cg.v2.f32 {%0, %1}, [%2];"
                     : "=f"(c.x), "=f"(c.y) : "l"(p));
    }
    __syncthreads();   // reuse wsum safely
    c = block_scan_128(c, wsum);
    float u = fmaxf(c.x * CXU, c.y * CYU);
    u = fminf(fmaxf(u, 0.5f), 2.0f);
    g_util[t * NUM_BINS + b] = u;
}

// Per movable node: 3 x-rows, each read as an aligned 4-bin window via two
// LDG.64; window bins weighted by the natural overlap (0 outside the span).
__global__ void node_kernel(const float* __restrict__ pos,
                            const float* __restrict__ nszx,
                            const float* __restrict__ nszy,
                            float* __restrict__ out) {
    int m = blockIdx.x * blockDim.x + threadIdx.x;
    if (m >= NUM_MOVABLE) return;
    if (m == 0) g_ctr = 0;                    // reset scan barrier for next replay
    float nx = __ldg(pos + m), ny = __ldg(pos + m + NUM_NODES);
    float sx = __ldg(nszx + m), sy = __ldg(nszy + m);
    float xh = nx + sx, yh = ny + sy;

    int x0 = bin_of(nx);
    int y0 = bin_of(ny);
    int ye = min(y0 & ~1, NUM_BINS - 4);      // aligned 4-bin y-window

    float wy[4];
    #pragma unroll
    for (int j = 0; j < 4; j++) {
        float by = (float)(ye + j) * SB;
        wy[j] = fmaxf(fminf(by + SB, yh) - fmaxf(by, ny), 0.f);
    }

    float acc = 0.f;
    #pragma unroll
    for (int k = 0; k < 3; k++) {
        float bx = (float)(x0 + k) * SB;
        float ox = fmaxf(fminf(bx + SB, xh) - fmaxf(bx, nx), 0.f);
        int row = min(x0 + k, NUM_BINS - 1) * NUM_BINS;
        float2 u01 = *(const float2*)&g_util[row + ye];
        float2 u23 = *(const float2*)&g_util[row + ye + 2];
        float a2 = wy[0] * u01.x + wy[1] * u01.y + wy[2] * u23.x + wy[3] * u23.y;
        acc += ox * a2;
    }
    out[m] = acc;
}

extern "C" void kernel_launch(void* const* d_in, const int* in_sizes, int n_in,
                              void* d_out, int out_size) {
    const float* pos          = (const float*)d_in[0];
    const float* pin_pos      = (const float*)d_in[1];
    const float* node_size_x  = (const float*)d_in[2];
    const float* node_size_y  = (const float*)d_in[3];
    const float* net_weights  = (const float*)d_in[4];
    const int*   netpin_start = (const int*)d_in[5];
    const int*   flat_netpin  = (const int*)d_in[6];
    float* out = (float*)d_out;

    prep_kernel<<<(NUM_PINS + 255) / 256, 256>>>(pin_pos);
    net_kernel<<<(NUM_NETS * 2 + 255) / 256, 256>>>(net_weights,
                                                    netpin_start, flat_netpin);
    scan_fused_kernel<<<NUM_BINS, NUM_BINS>>>();
    node_kernel<<<(NUM_MOVABLE + 255) / 256, 256>>>(pos, node_size_x,
                                                    node_size_y, out);
}

// round 13
// speedup vs baseline: 1.0762x; 1.0762x over previous
#include <cuda_runtime.h>
#include <math.h>

#define NUM_BINS    128
#define NUM_NETS    100000
#define NUM_NODES   200000
#define NUM_MOVABLE 180000
#define NUM_PINS    400000
#define NREP        8               // replicas of each diff array

#define SB       7.8125f            // bin size (1000/128), exact in fp32
#define INV_SB   0.128f             // approx 1/SB; corrected in bin_of
#define BIN_AREA 61.03515625f       // SB*SB, exact
#define CXU (1.0f / (BIN_AREA * 1.5f))
#define CYU (1.0f / (BIN_AREA * 1.4f))

#define NODE_BLK 512
#define NODE_GRID ((NUM_MOVABLE + NODE_BLK - 1) / NODE_BLK)

// Scratch. All zero at load; scan kernel re-zeroes each invocation.
__device__ __align__(16) float2 g_de[NREP][NUM_BINS * NUM_BINS];  // even-y pairs
__device__ __align__(16) float2 g_do[NREP][NUM_BINS * NUM_BINS];  // odd-y pairs, slot k = bin k+1
__device__ float2 g_pref[NUM_BINS * NUM_BINS];               // after y-prefix
__device__ __align__(16) float g_util[NUM_BINS * NUM_BINS];  // final util [x*128+y]
__device__ int    g_ctr;                                     // scan grid barrier (reset by node_kernel)

__device__ __forceinline__ int bin_of(float v) {
    int b = (int)(v * INV_SB);
    b = max(0, min(NUM_BINS - 1, b));
    if (v < (float)b * SB) b--;
    else if (v >= (float)(b + 1) * SB) b++;
    return max(0, min(NUM_BINS - 1, b));
}

__device__ __forceinline__ void red_add4(float2* addr, float a0, float b0,
                                         float a1, float b1) {
    asm volatile("red.global.add.v4.f32 [%0], {%1, %2, %3, %4};"
                 :: "l"(addr), "f"(a0), "f"(b0), "f"(a1), "f"(b1) : "memory");
}

// One v4 RED covering logical bins (y, y+1) of x-row `row`, replica `rep`.
__device__ __forceinline__ void emit_pair(int rep, int row, int y,
                                          float a0, float b0, float a1, float b1) {
    if ((y & 1) == 0) {
        red_add4(&g_de[rep][row * NUM_BINS + y], a0, b0, a1, b1);
    } else {
        red_add4(&g_do[rep][row * NUM_BINS + (y - 1)], a0, b0, a1, b1);
    }
}

// Quad-reduced bbox -> this lane's 2 v4 updates; lane q owns x-row q.
__device__ __forceinline__ void process_net(int n, int q, float w,
                                            float xmn, float xmx,
                                            float ymn, float ymx) {
    float dx = xmx - xmn, dy = ymx - ymn;
    float cx = (dy > 0.f) ? (w / dy) : 0.f;   // scales map_x
    float cy = (dx > 0.f) ? (w / dx) : 0.f;   // scales map_y
    if (cx == 0.f && cy == 0.f) return;       // also catches empty nets (inf bbox)

    int x0 = bin_of(xmn), x1 = bin_of(xmx);
    int y0 = bin_of(ymn), y1 = bin_of(ymx);

    float v0x = (float)(x0 + 1) * SB - xmn;
    float v1x = xmx - (float)x1 * SB;
    float v0y = (float)(y0 + 1) * SB - ymn;
    float v1y = ymx - (float)y1 * SB;

    float yv0 = v0y, yv1 = SB - v0y, yv2 = v1y - SB, yv3 = -v1y;

    int   xp   = ((q & 2) ? x1 : x0) + (q & 1);
    float base = (q & 2) ? (v1x - SB) : v0x;
    float alt  = (q & 2) ? (-v1x)     : (SB - v0x);
    float xv   = (q & 1) ? alt : base;

    if (xp < NUM_BINS) {
        int rep = n & (NREP - 1);
        float a = xv * cx, b = xv * cy;
        emit_pair(rep, xp, y0, a * yv0, b * yv0, a * yv1, b * yv1);
        emit_pair(rep, xp, y1, a * yv2, b * yv2, a * yv3, b * yv3);
    }
}

// One quad of lanes handles TWO nets (2k, 2k+1): each lane issues its pin
// gathers for both nets up front, then two quad reductions and emissions.
__global__ void net_kernel(const float* __restrict__ pin_pos,
                           const float* __restrict__ net_weights,
                           const int*   __restrict__ netpin_start,
                           const int*   __restrict__ flat_netpin) {
    int gid  = blockIdx.x * blockDim.x + threadIdx.x;
    int pair = gid >> 2;           // net pair id
    int q    = gid & 3;            // lane-in-quad
    int n0   = pair * 2;
    if (n0 >= NUM_NETS) return;
    int n1 = n0 + 1;               // NUM_NETS is even

    int s0 = __ldg(netpin_start + n0);
    int e0 = __ldg(netpin_start + n0 + 1);
    int s1 = __ldg(netpin_start + n1);
    int e1 = __ldg(netpin_start + n1 + 1);

    float xmn0 = 3.4e38f, xmx0 = -3.4e38f, ymn0 = 3.4e38f, ymx0 = -3.4e38f;
    float xmn1 = 3.4e38f, xmx1 = -3.4e38f, ymn1 = 3.4e38f, ymx1 = -3.4e38f;

    if ((e0 - s0 == 4) && (e1 - s1 == 4)) {   // hot path for this dataset
        int p0 = __ldg(flat_netpin + s0 + q);
        int p1 = __ldg(flat_netpin + s1 + q);
        float px0 = __ldg(pin_pos + p0);
        float py0 = __ldg(pin_pos + p0 + NUM_PINS);
        float px1 = __ldg(pin_pos + p1);
        float py1 = __ldg(pin_pos + p1 + NUM_PINS);
        xmn0 = px0; xmx0 = px0; ymn0 = py0; ymx0 = py0;
        xmn1 = px1; xmx1 = px1; ymn1 = py1; ymx1 = py1;
    } else {                                   // general fallback
        for (int i = s0 + q; i < e0; i += 4) {
            int p = __ldg(flat_netpin + i);
            float px = __ldg(pin_pos + p);
            float py = __ldg(pin_pos + p + NUM_PINS);
            xmn0 = fminf(xmn0, px); xmx0 = fmaxf(xmx0, px);
            ymn0 = fminf(ymn0, py); ymx0 = fmaxf(ymx0, py);
        }
        for (int i = s1 + q; i < e1; i += 4) {
            int p = __ldg(flat_netpin + i);
            float px = __ldg(pin_pos + p);
            float py = __ldg(pin_pos + p + NUM_PINS);
            xmn1 = fminf(xmn1, px); xmx1 = fmaxf(xmx1, px);
            ymn1 = fminf(ymn1, py); ymx1 = fmaxf(ymx1, py);
        }
    }

    #pragma unroll
    for (int o = 1; o <= 2; o <<= 1) {
        xmn0 = fminf(xmn0, __shfl_xor_sync(0xffffffffu, xmn0, o));
        xmx0 = fmaxf(xmx0, __shfl_xor_sync(0xffffffffu, xmx0, o));
        ymn0 = fminf(ymn0, __shfl_xor_sync(0xffffffffu, ymn0, o));
        ymx0 = fmaxf(ymx0, __shfl_xor_sync(0xffffffffu, ymx0, o));
        xmn1 = fminf(xmn1, __shfl_xor_sync(0xffffffffu, xmn1, o));
        xmx1 = fmaxf(xmx1, __shfl_xor_sync(0xffffffffu, xmx1, o));
        ymn1 = fminf(ymn1, __shfl_xor_sync(0xffffffffu, ymn1, o));
        ymx1 = fmaxf(ymx1, __shfl_xor_sync(0xffffffffu, ymx1, o));
    }

    float w0 = __ldg(net_weights + n0);
    float w1 = __ldg(net_weights + n1);

    process_net(n0, q, w0, xmn0, xmx0, ymn0, ymx0);
    process_net(n1, q, w1, xmn1, xmx1, ymn1, ymx1);
}

__device__ __forceinline__ float2 block_scan_128(float2 v, float2* wsum) {
    int t = threadIdx.x, lane = t & 31, w = t >> 5;
    #pragma unroll
    for (int o = 1; o < 32; o <<= 1) {
        float ax = __shfl_up_sync(0xffffffffu, v.x, o);
        float ay = __shfl_up_sync(0xffffffffu, v.y, o);
        if (lane >= o) { v.x += ax; v.y += ay; }
    }
    if (lane == 31) wsum[w] = v;
    __syncthreads();
    float ox = 0.f, oy = 0.f;
    #pragma unroll
    for (int k = 0; k < 3; k++)
        if (w > k) { ox += wsum[k].x; oy += wsum[k].y; }
    v.x += ox; v.y += oy;
    return v;
}

// 128 blocks (all wave-1 resident). Phase 1: front-batch ALL 32 replica loads
// for slot t (MLP 32 vs pending-RMW latency), sum, zero exactly what was read,
// shift odd-phase sums by one thread to realign logical bins, y-prefix scan.
// Grid barrier. Phase 2: x-prefix + util.
__global__ void scan_fused_kernel() {
    __shared__ float2 wsum[4];
    __shared__ float2 wdo[4];
    int b = blockIdx.x, t = threadIdx.x;
    int lane = t & 31, w = t >> 5;
    int idx = b * NUM_BINS + t;

    float2 de[NREP], dd[NREP];
    #pragma unroll
    for (int r = 0; r < NREP; r++) de[r] = g_de[r][idx];
    #pragma unroll
    for (int r = 0; r < NREP; r++) dd[r] = g_do[r][idx];

    float2 v  = make_float2(0.f, 0.f);
    float2 vo = make_float2(0.f, 0.f);
    #pragma unroll
    for (int r = 0; r < NREP; r++) {
        v.x  += de[r].x;  v.y  += de[r].y;
        vo.x += dd[r].x;  vo.y += dd[r].y;
    }
    #pragma unroll
    for (int r = 0; r < NREP; r++) {
        g_de[r][idx] = make_float2(0.f, 0.f);
        g_do[r][idx] = make_float2(0.f, 0.f);
    }

    // logical bin t = de_sum(t) + do_sum(t-1)
    float sx = __shfl_up_sync(0xffffffffu, vo.x, 1);
    float sy = __shfl_up_sync(0xffffffffu, vo.y, 1);
    if (lane == 31) wdo[w] = vo;
    __syncthreads();
    if (lane == 0) {
        if (w > 0) { sx = wdo[w - 1].x; sy = wdo[w - 1].y; }
        else       { sx = 0.f;          sy = 0.f; }
    }
    v.x += sx; v.y += sy;

    v = block_scan_128(v, wsum);
    g_pref[idx] = v;

    __threadfence();
    __syncthreads();
    if (t == 0) {
        atomicAdd(&g_ctr, 1);
        while (atomicAdd(&g_ctr, 0) < NUM_BINS) __nanosleep(40);
    }
    __syncthreads();
    __threadfence();

    float2 c;
    {
        const float2* p = g_pref + t * NUM_BINS + b;
        asm volatile("ld.global.cg.v2.f32 {%0, %1}, [%2];"
                     : "=f"(c.x), "=f"(c.y) : "l"(p));
    }
    __syncthreads();   // reuse wsum safely
    c = block_scan_128(c, wsum);
    float u = fmaxf(c.x * CXU, c.y * CYU);
    u = fminf(fmaxf(u, 0.5f), 2.0f);
    g_util[t * NUM_BINS + b] = u;
}

// Per movable node. Each block first caches the full 64KB util table in
// dynamic shared memory (coalesced float4), so the 9 random-position reads
// go through the LDS path (bank model) instead of the L1tex wavefront queue.
__global__ void node_kernel(const float* __restrict__ pos,
                            const float* __restrict__ nszx,
                            const float* __restrict__ nszy,
                            float* __restrict__ out) {
    extern __shared__ float s_util[];
    int tid = threadIdx.x;

    // Cache util: 16384 floats = 4096 float4, 512 threads x 8 each.
    #pragma unroll
    for (int i = tid; i < (NUM_BINS * NUM_BINS) / 4; i += NODE_BLK)
        ((float4*)s_util)[i] = ((const float4*)g_util)[i];
    __syncthreads();

    int m = blockIdx.x * NODE_BLK + tid;
    if (m >= NUM_MOVABLE) return;
    if (m == 0) g_ctr = 0;                    // reset scan barrier for next replay

    float nx = __ldg(pos + m), ny = __ldg(pos + m + NUM_NODES);
    float sx = __ldg(nszx + m), sy = __ldg(nszy + m);
    float xh = nx + sx, yh = ny + sy;

    int x0 = bin_of(nx);
    int y0 = bin_of(ny);

    float wy[3];
    int   yi[3];
    #pragma unroll
    for (int j = 0; j < 3; j++) {
        float by = (float)(y0 + j) * SB;
        wy[j] = fmaxf(fminf(by + SB, yh) - fmaxf(by, ny), 0.f);
        yi[j] = min(y0 + j, NUM_BINS - 1);
    }

    float acc = 0.f;
    #pragma unroll
    for (int k = 0; k < 3; k++) {
        float bx = (float)(x0 + k) * SB;
        float ox = fmaxf(fminf(bx + SB, xh) - fmaxf(bx, nx), 0.f);
        int row = min(x0 + k, NUM_BINS - 1) * NUM_BINS;
        float a2 = wy[0] * s_util[row + yi[0]]
                 + wy[1] * s_util[row + yi[1]]
                 + wy[2] * s_util[row + yi[2]];
        acc += ox * a2;
    }
    out[m] = acc;
}

extern "C" void kernel_launch(void* const* d_in, const int* in_sizes, int n_in,
                              void* d_out, int out_size) {
    const float* pos          = (const float*)d_in[0];
    const float* pin_pos      = (const float*)d_in[1];
    const float* node_size_x  = (const float*)d_in[2];
    const float* node_size_y  = (const float*)d_in[3];
    const float* net_weights  = (const float*)d_in[4];
    const int*   netpin_start = (const int*)d_in[5];
    const int*   flat_netpin  = (const int*)d_in[6];
    float* out = (float*)d_out;

    // Allow 64KB dynamic smem for node_kernel (host-side attribute; idempotent).
    cudaFuncSetAttribute(node_kernel,
                         cudaFuncAttributeMaxDynamicSharedMemorySize,
                         NUM_BINS * NUM_BINS * (int)sizeof(float));

    net_kernel<<<(NUM_NETS * 2 + 255) / 256, 256>>>(pin_pos, net_weights,
                                                    netpin_start, flat_netpin);
    scan_fused_kernel<<<NUM_BINS, NUM_BINS>>>();
    node_kernel<<<NODE_GRID, NODE_BLK,
                  NUM_BINS * NUM_BINS * sizeof(float)>>>(pos, node_size_x,
                                                         node_size_y, out);
}

// round 14
// speedup vs baseline: 1.0779x; 1.0015x over previous
#include <cuda_runtime.h>
#include <math.h>

#define NUM_BINS    128
#define NUM_NETS    100000
#define NUM_NODES   200000
#define NUM_MOVABLE 180000
#define NUM_PINS    400000
#define NREP        8               // replicas of each diff array

#define SB       7.8125f            // bin size (1000/128), exact in fp32
#define INV_SB   0.128f             // approx 1/SB; corrected in bin_of
#define BIN_AREA 61.03515625f       // SB*SB, exact
#define CXU (1.0f / (BIN_AREA * 1.5f))
#define CYU (1.0f / (BIN_AREA * 1.4f))

#define NODE_BLK  512
#define NODE_GRID 148               // persistent: one block per SM

// Scratch. All zero at load; scan kernel re-zeroes each invocation.
__device__ __align__(16) float2 g_de[NREP][NUM_BINS * NUM_BINS];  // even-y pairs
__device__ __align__(16) float2 g_do[NREP][NUM_BINS * NUM_BINS];  // odd-y pairs, slot k = bin k+1
__device__ float2 g_pref[NUM_BINS * NUM_BINS];               // after y-prefix
__device__ __align__(16) float g_util[NUM_BINS * NUM_BINS];  // final util [x*128+y]
__device__ int    g_ctr;                                     // scan grid barrier (reset by node_kernel)

__device__ __forceinline__ int bin_of(float v) {
    int b = (int)(v * INV_SB);
    b = max(0, min(NUM_BINS - 1, b));
    if (v < (float)b * SB) b--;
    else if (v >= (float)(b + 1) * SB) b++;
    return max(0, min(NUM_BINS - 1, b));
}

__device__ __forceinline__ void red_add4(float2* addr, float a0, float b0,
                                         float a1, float b1) {
    asm volatile("red.global.add.v4.f32 [%0], {%1, %2, %3, %4};"
                 :: "l"(addr), "f"(a0), "f"(b0), "f"(a1), "f"(b1) : "memory");
}

// One v4 RED covering logical bins (y, y+1) of x-row `row`, replica `rep`.
__device__ __forceinline__ void emit_pair(int rep, int row, int y,
                                          float a0, float b0, float a1, float b1) {
    if ((y & 1) == 0) {
        red_add4(&g_de[rep][row * NUM_BINS + y], a0, b0, a1, b1);
    } else {
        red_add4(&g_do[rep][row * NUM_BINS + (y - 1)], a0, b0, a1, b1);
    }
}

// Quad-reduced bbox -> this lane's 2 v4 updates; lane q owns x-row q.
__device__ __forceinline__ void process_net(int n, int q, float w,
                                            float xmn, float xmx,
                                            float ymn, float ymx) {
    float dx = xmx - xmn, dy = ymx - ymn;
    float cx = (dy > 0.f) ? (w / dy) : 0.f;   // scales map_x
    float cy = (dx > 0.f) ? (w / dx) : 0.f;   // scales map_y
    if (cx == 0.f && cy == 0.f) return;       // also catches empty nets (inf bbox)

    int x0 = bin_of(xmn), x1 = bin_of(xmx);
    int y0 = bin_of(ymn), y1 = bin_of(ymx);

    float v0x = (float)(x0 + 1) * SB - xmn;
    float v1x = xmx - (float)x1 * SB;
    float v0y = (float)(y0 + 1) * SB - ymn;
    float v1y = ymx - (float)y1 * SB;

    float yv0 = v0y, yv1 = SB - v0y, yv2 = v1y - SB, yv3 = -v1y;

    int   xp   = ((q & 2) ? x1 : x0) + (q & 1);
    float base = (q & 2) ? (v1x - SB) : v0x;
    float alt  = (q & 2) ? (-v1x)     : (SB - v0x);
    float xv   = (q & 1) ? alt : base;

    if (xp < NUM_BINS) {
        int rep = n & (NREP - 1);
        float a = xv * cx, b = xv * cy;
        emit_pair(rep, xp, y0, a * yv0, b * yv0, a * yv1, b * yv1);
        emit_pair(rep, xp, y1, a * yv2, b * yv2, a * yv3, b * yv3);
    }
}

// One quad of lanes handles TWO nets (2k, 2k+1): each lane issues its pin
// gathers for both nets up front, then two quad reductions and emissions.
__global__ void net_kernel(const float* __restrict__ pin_pos,
                           const float* __restrict__ net_weights,
                           const int*   __restrict__ netpin_start,
                           const int*   __restrict__ flat_netpin) {
    int gid  = blockIdx.x * blockDim.x + threadIdx.x;
    int pair = gid >> 2;           // net pair id
    int q    = gid & 3;            // lane-in-quad
    int n0   = pair * 2;
    if (n0 >= NUM_NETS) return;
    int n1 = n0 + 1;               // NUM_NETS is even

    int s0 = __ldg(netpin_start + n0);
    int e0 = __ldg(netpin_start + n0 + 1);
    int s1 = __ldg(netpin_start + n1);
    int e1 = __ldg(netpin_start + n1 + 1);

    float xmn0 = 3.4e38f, xmx0 = -3.4e38f, ymn0 = 3.4e38f, ymx0 = -3.4e38f;
    float xmn1 = 3.4e38f, xmx1 = -3.4e38f, ymn1 = 3.4e38f, ymx1 = -3.4e38f;

    if ((e0 - s0 == 4) && (e1 - s1 == 4)) {   // hot path for this dataset
        int p0 = __ldg(flat_netpin + s0 + q);
        int p1 = __ldg(flat_netpin + s1 + q);
        float px0 = __ldg(pin_pos + p0);
        float py0 = __ldg(pin_pos + p0 + NUM_PINS);
        float px1 = __ldg(pin_pos + p1);
        float py1 = __ldg(pin_pos + p1 + NUM_PINS);
        xmn0 = px0; xmx0 = px0; ymn0 = py0; ymx0 = py0;
        xmn1 = px1; xmx1 = px1; ymn1 = py1; ymx1 = py1;
    } else {                                   // general fallback
        for (int i = s0 + q; i < e0; i += 4) {
            int p = __ldg(flat_netpin + i);
            float px = __ldg(pin_pos + p);
            float py = __ldg(pin_pos + p + NUM_PINS);
            xmn0 = fminf(xmn0, px); xmx0 = fmaxf(xmx0, px);
            ymn0 = fminf(ymn0, py); ymx0 = fmaxf(ymx0, py);
        }
        for (int i = s1 + q; i < e1; i += 4) {
            int p = __ldg(flat_netpin + i);
            float px = __ldg(pin_pos + p);
            float py = __ldg(pin_pos + p + NUM_PINS);
            xmn1 = fminf(xmn1, px); xmx1 = fmaxf(xmx1, px);
            ymn1 = fminf(ymn1, py); ymx1 = fmaxf(ymx1, py);
        }
    }

    #pragma unroll
    for (int o = 1; o <= 2; o <<= 1) {
        xmn0 = fminf(xmn0, __shfl_xor_sync(0xffffffffu, xmn0, o));
        xmx0 = fmaxf(xmx0, __shfl_xor_sync(0xffffffffu, xmx0, o));
        ymn0 = fminf(ymn0, __shfl_xor_sync(0xffffffffu, ymn0, o));
        ymx0 = fmaxf(ymx0, __shfl_xor_sync(0xffffffffu, ymx0, o));
        xmn1 = fminf(xmn1, __shfl_xor_sync(0xffffffffu, xmn1, o));
        xmx1 = fmaxf(xmx1, __shfl_xor_sync(0xffffffffu, xmx1, o));
        ymn1 = fminf(ymn1, __shfl_xor_sync(0xffffffffu, ymn1, o));
        ymx1 = fmaxf(ymx1, __shfl_xor_sync(0xffffffffu, ymx1, o));
    }

    float w0 = __ldg(net_weights + n0);
    float w1 = __ldg(net_weights + n1);

    process_net(n0, q, w0, xmn0, xmx0, ymn0, ymx0);
    process_net(n1, q, w1, xmn1, xmx1, ymn1, ymx1);
}

__device__ __forceinline__ float2 block_scan_128(float2 v, float2* wsum) {
    int t = threadIdx.x, lane = t & 31, w = t >> 5;
    #pragma unroll
    for (int o = 1; o < 32; o <<= 1) {
        float ax = __shfl_up_sync(0xffffffffu, v.x, o);
        float ay = __shfl_up_sync(0xffffffffu, v.y, o);
        if (lane >= o) { v.x += ax; v.y += ay; }
    }
    if (lane == 31) wsum[w] = v;
    __syncthreads();
    float ox = 0.f, oy = 0.f;
    #pragma unroll
    for (int k = 0; k < 3; k++)
        if (w > k) { ox += wsum[k].x; oy += wsum[k].y; }
    v.x += ox; v.y += oy;
    return v;
}

// 128 blocks (all wave-1 resident). Phase 1: front-batch ALL 32 replica loads
// for slot t (MLP 32 vs pending-RMW latency), sum, zero exactly what was read,
// shift odd-phase sums by one thread to realign logical bins, y-prefix scan.
// Grid barrier. Phase 2: x-prefix + util.
__global__ void scan_fused_kernel() {
    __shared__ float2 wsum[4];
    __shared__ float2 wdo[4];
    int b = blockIdx.x, t = threadIdx.x;
    int lane = t & 31, w = t >> 5;
    int idx = b * NUM_BINS + t;

    float2 de[NREP], dd[NREP];
    #pragma unroll
    for (int r = 0; r < NREP; r++) de[r] = g_de[r][idx];
    #pragma unroll
    for (int r = 0; r < NREP; r++) dd[r] = g_do[r][idx];

    float2 v  = make_float2(0.f, 0.f);
    float2 vo = make_float2(0.f, 0.f);
    #pragma unroll
    for (int r = 0; r < NREP; r++) {
        v.x  += de[r].x;  v.y  += de[r].y;
        vo.x += dd[r].x;  vo.y += dd[r].y;
    }
    #pragma unroll
    for (int r = 0; r < NREP; r++) {
        g_de[r][idx] = make_float2(0.f, 0.f);
        g_do[r][idx] = make_float2(0.f, 0.f);
    }

    // logical bin t = de_sum(t) + do_sum(t-1)
    float sx = __shfl_up_sync(0xffffffffu, vo.x, 1);
    float sy = __shfl_up_sync(0xffffffffu, vo.y, 1);
    if (lane == 31) wdo[w] = vo;
    __syncthreads();
    if (lane == 0) {
        if (w > 0) { sx = wdo[w - 1].x; sy = wdo[w - 1].y; }
        else       { sx = 0.f;          sy = 0.f; }
    }
    v.x += sx; v.y += sy;

    v = block_scan_128(v, wsum);
    g_pref[idx] = v;

    __threadfence();
    __syncthreads();
    if (t == 0) {
        atomicAdd(&g_ctr, 1);
        while (atomicAdd(&g_ctr, 0) < NUM_BINS) __nanosleep(40);
    }
    __syncthreads();
    __threadfence();

    float2 c;
    {
        const float2* p = g_pref + t * NUM_BINS + b;
        asm volatile("ld.global.cg.v2.f32 {%0, %1}, [%2];"
                     : "=f"(c.x), "=f"(c.y) : "l"(p));
    }
    __syncthreads();   // reuse wsum safely
    c = block_scan_128(c, wsum);
    float u = fmaxf(c.x * CXU, c.y * CYU);
    u = fminf(fmaxf(u, 0.5f), 2.0f);
    g_util[t * NUM_BINS + b] = u;
}

// Persistent node kernel: 148 blocks (one/SM) x 512 threads. Each block
// caches the 64KB util table in shared memory ONCE (9.5MB total fill vs
// 22MB at 352 blocks), then grid-strides over ~1216 nodes; the 9 taps per
// node run on the LDS path instead of the L1tex wavefront queue.
__global__ void node_kernel(const float* __restrict__ pos,
                            const float* __restrict__ nszx,
                            const float* __restrict__ nszy,
                            float* __restrict__ out) {
    extern __shared__ float s_util[];
    int tid = threadIdx.x;

    #pragma unroll
    for (int i = tid; i < (NUM_BINS * NUM_BINS) / 4; i += NODE_BLK)
        ((float4*)s_util)[i] = ((const float4*)g_util)[i];
    if (blockIdx.x == 0 && tid == 0) g_ctr = 0;  // reset scan barrier for replay
    __syncthreads();

    for (int m = blockIdx.x * NODE_BLK + tid; m < NUM_MOVABLE;
         m += NODE_GRID * NODE_BLK) {
        float nx = __ldg(pos + m), ny = __ldg(pos + m + NUM_NODES);
        float sx = __ldg(nszx + m), sy = __ldg(nszy + m);
        float xh = nx + sx, yh = ny + sy;

        int x0 = bin_of(nx);
        int y0 = bin_of(ny);

        float wy[3];
        int   yi[3];
        #pragma unroll
        for (int j = 0; j < 3; j++) {
            float by = (float)(y0 + j) * SB;
            wy[j] = fmaxf(fminf(by + SB, yh) - fmaxf(by, ny), 0.f);
            yi[j] = min(y0 + j, NUM_BINS - 1);
        }

        float acc = 0.f;
        #pragma unroll
        for (int k = 0; k < 3; k++) {
            float bx = (float)(x0 + k) * SB;
            float ox = fmaxf(fminf(bx + SB, xh) - fmaxf(bx, nx), 0.f);
            int row = min(x0 + k, NUM_BINS - 1) * NUM_BINS;
            float a2 = wy[0] * s_util[row + yi[0]]
                     + wy[1] * s_util[row + yi[1]]
                     + wy[2] * s_util[row + yi[2]];
            acc += ox * a2;
        }
        out[m] = acc;
    }
}

extern "C" void kernel_launch(void* const* d_in, const int* in_sizes, int n_in,
                              void* d_out, int out_size) {
    const float* pos          = (const float*)d_in[0];
    const float* pin_pos      = (const float*)d_in[1];
    const float* node_size_x  = (const float*)d_in[2];
    const float* node_size_y  = (const float*)d_in[3];
    const float* net_weights  = (const float*)d_in[4];
    const int*   netpin_start = (const int*)d_in[5];
    const int*   flat_netpin  = (const int*)d_in[6];
    float* out = (float*)d_out;

    // Allow 64KB dynamic smem for node_kernel (host-side attribute; idempotent).
    cudaFuncSetAttribute(node_kernel,
                         cudaFuncAttributeMaxDynamicSharedMemorySize,
                         NUM_BINS * NUM_BINS * (int)sizeof(float));

    net_kernel<<<(NUM_NETS * 2 + 255) / 256, 256>>>(pin_pos, net_weights,
                                                    netpin_start, flat_netpin);
    scan_fused_kernel<<<NUM_BINS, NUM_BINS>>>();
    node_kernel<<<NODE_GRID, NODE_BLK,
                  NUM_BINS * NUM_BINS * sizeof(float)>>>(pos, node_size_x,
                                                         node_size_y, out);
}